// round 12
// baseline (speedup 1.0000x reference)
#include <cuda_runtime.h>
#include <cuda_bf16.h>

#define NPARAMS 1280

// out[i] = Param_b[b_params[i]]   (also the zero-init for the scatter)
__global__ void bias_init_kernel(const float* __restrict__ Pb,
                                 const int*   __restrict__ bidx,
                                 float*       __restrict__ out,
                                 int n) {
    int v = blockIdx.x * blockDim.x + threadIdx.x;   // vec4 index
    int nvec = n >> 2;
    if (v < nvec) {
        int4 b = ((const int4*)bidx)[v];
        float4 o;
        o.x = __ldg(&Pb[b.x]);
        o.y = __ldg(&Pb[b.y]);
        o.z = __ldg(&Pb[b.z]);
        o.w = __ldg(&Pb[b.w]);
        ((float4*)out)[v] = o;
    }
    // scalar tail (defensive; n = 262144 here)
    int tail = n & 3;
    if (v < tail) {
        int i = n - tail + v;
        out[i] = __ldg(&Pb[__ldg(&bidx[i])]);
    }
}

// For each edge e: out[rows[e]] += Param_W[params[e]] * x[cols[e]]
// 8 edges/thread/iter in two 4-edge half-batches with short live ranges so the
// kernel fits 32 regs -> 8 CTAs/SM (2048 threads) for max in-flight L2 pressure.
__global__ void __launch_bounds__(256, 8)
edge_scatter_kernel(const float* __restrict__ x,
                    const float* __restrict__ Pw,
                    const int*   __restrict__ rows,
                    const int*   __restrict__ cols,
                    const int*   __restrict__ params,
                    float*       __restrict__ out,
                    int nvec,   // E / 4
                    int tail,   // E % 4
                    int E) {
    __shared__ float sPw[NPARAMS];
    for (int i = threadIdx.x; i < NPARAMS; i += blockDim.x)
        sPw[i] = Pw[i];
    __syncthreads();

    const int4* __restrict__ rows4   = (const int4*)rows;
    const int4* __restrict__ cols4   = (const int4*)cols;
    const int4* __restrict__ params4 = (const int4*)params;

    int gtid   = blockIdx.x * blockDim.x + threadIdx.x;
    int stride = gridDim.x * blockDim.x;

    for (int v = gtid; v < nvec; v += 2 * stride) {
        int  v2 = v + stride;
        bool h2 = (v2 < nvec);

        // ---- half-batch 0 ----
        int4 c0 = __ldcs(&cols4[v]);
        // issue gathers for batch 0 immediately
        float g0 = __ldg(&x[c0.x]);
        float g1 = __ldg(&x[c0.y]);
        float g2 = __ldg(&x[c0.z]);
        float g3 = __ldg(&x[c0.w]);

        // ---- prefetch half-batch 1 gathers while batch 0 is in flight ----
        float g4, g5, g6, g7;
        int4  p1, c1;
        if (h2) {
            c1 = __ldcs(&cols4[v2]);
            g4 = __ldg(&x[c1.x]);
            g5 = __ldg(&x[c1.y]);
            g6 = __ldg(&x[c1.z]);
            g7 = __ldg(&x[c1.w]);
        }

        // ---- retire half-batch 0 (REDG is fire-and-forget) ----
        {
            int4 p0 = __ldcs(&params4[v]);
            int4 r0 = __ldcs(&rows4[v]);
            atomicAdd(&out[r0.x], sPw[p0.x] * g0);
            atomicAdd(&out[r0.y], sPw[p0.y] * g1);
            atomicAdd(&out[r0.z], sPw[p0.z] * g2);
            atomicAdd(&out[r0.w], sPw[p0.w] * g3);
        }

        // ---- retire half-batch 1 ----
        if (h2) {
            p1 = __ldcs(&params4[v2]);
            int4 r1 = __ldcs(&rows4[v2]);
            atomicAdd(&out[r1.x], sPw[p1.x] * g4);
            atomicAdd(&out[r1.y], sPw[p1.y] * g5);
            atomicAdd(&out[r1.z], sPw[p1.z] * g6);
            atomicAdd(&out[r1.w], sPw[p1.w] * g7);
        }
    }

    // Tail edges (E % 4 != 0) — defensive; E = 2^24 here.
    if (gtid < tail) {
        int e = E - tail + gtid;
        float val = sPw[params[e]] * __ldg(&x[cols[e]]);
        atomicAdd(&out[rows[e]], val);
    }
}

extern "C" void kernel_launch(void* const* d_in, const int* in_sizes, int n_in,
                              void* d_out, int out_size) {
    // metadata order: x, Param_W, Param_b, w_rows, w_cols, w_params, b_params
    const float* x        = (const float*)d_in[0];
    const float* Param_W  = (const float*)d_in[1];
    const float* Param_b  = (const float*)d_in[2];
    const int*   w_rows   = (const int*)d_in[3];
    const int*   w_cols   = (const int*)d_in[4];
    const int*   w_params = (const int*)d_in[5];
    const int*   b_params = (const int*)d_in[6];
    float*       out      = (float*)d_out;

    const int N = out_size;     // 262144
    const int E = in_sizes[3];  // 16777216

    // 1) bias init (ordered before scatter on the same stream)
    {
        int threads = 256;
        int nvec    = N >> 2;
        int blocks  = (nvec + threads - 1) / threads;
        if (blocks < 1) blocks = 1;
        bias_init_kernel<<<blocks, threads>>>(Param_b, b_params, out, N);
    }

    // 2) edge scatter: single full wave at 8 CTAs/SM x 152 SMs = 2048 thr/SM
    {
        int nvec    = E / 4;
        int tail    = E - nvec * 4;
        int threads = 256;
        int blocks  = 152 * 8;
        edge_scatter_kernel<<<blocks, threads>>>(x, Param_W, w_rows, w_cols,
                                                 w_params, out, nvec, tail, E);
    }
}

// round 14
// speedup vs baseline: 1.0296x; 1.0296x over previous
#include <cuda_runtime.h>
#include <cuda_bf16.h>

#define NPARAMS 1280

// out[i] = Param_b[b_params[i]]   (also the zero-init for the scatter)
__global__ void bias_init_kernel(const float* __restrict__ Pb,
                                 const int*   __restrict__ bidx,
                                 float*       __restrict__ out,
                                 int n) {
    int v = blockIdx.x * blockDim.x + threadIdx.x;   // vec4 index
    int nvec = n >> 2;
    if (v < nvec) {
        int4 b = ((const int4*)bidx)[v];
        float4 o;
        o.x = __ldg(&Pb[b.x]);
        o.y = __ldg(&Pb[b.y]);
        o.z = __ldg(&Pb[b.z]);
        o.w = __ldg(&Pb[b.w]);
        ((float4*)out)[v] = o;
    }
    // scalar tail (defensive; n = 262144 here)
    int tail = n & 3;
    if (v < tail) {
        int i = n - tail + v;
        out[i] = __ldg(&Pb[__ldg(&bidx[i])]);
    }
}

// For each edge e: out[rows[e]] += Param_W[params[e]] * x[cols[e]]
// 8 edges/thread/iter, 32 regs -> 8 CTAs/SM. Launched with PDL: the smem
// prologue overlaps bias_init; cudaGridDependencySynchronize() gates the
// first atomic on bias_init completion.
__global__ void __launch_bounds__(256, 8)
edge_scatter_kernel(const float* __restrict__ x,
                    const float* __restrict__ Pw,
                    const int*   __restrict__ rows,
                    const int*   __restrict__ cols,
                    const int*   __restrict__ params,
                    float*       __restrict__ out,
                    int nvec,   // E / 4
                    int tail,   // E % 4
                    int E) {
    __shared__ float sPw[NPARAMS];
    for (int i = threadIdx.x; i < NPARAMS; i += blockDim.x)
        sPw[i] = Pw[i];

    // Wait for bias_init (upstream PDL kernel) to complete before any atomic.
#if __CUDA_ARCH__ >= 900
    cudaGridDependencySynchronize();
#endif
    __syncthreads();

    const int4* __restrict__ rows4   = (const int4*)rows;
    const int4* __restrict__ cols4   = (const int4*)cols;
    const int4* __restrict__ params4 = (const int4*)params;

    int gtid   = blockIdx.x * blockDim.x + threadIdx.x;
    int stride = gridDim.x * blockDim.x;

    for (int v = gtid; v < nvec; v += 2 * stride) {
        int  v2 = v + stride;
        bool h2 = (v2 < nvec);

        // ---- half-batch 0 ----
        int4 c0 = __ldcs(&cols4[v]);
        float g0 = __ldg(&x[c0.x]);
        float g1 = __ldg(&x[c0.y]);
        float g2 = __ldg(&x[c0.z]);
        float g3 = __ldg(&x[c0.w]);

        // ---- prefetch half-batch 1 gathers while batch 0 is in flight ----
        float g4, g5, g6, g7;
        int4  c1;
        if (h2) {
            c1 = __ldcs(&cols4[v2]);
            g4 = __ldg(&x[c1.x]);
            g5 = __ldg(&x[c1.y]);
            g6 = __ldg(&x[c1.z]);
            g7 = __ldg(&x[c1.w]);
        }

        // ---- retire half-batch 0 (REDG is fire-and-forget) ----
        {
            int4 p0 = __ldcs(&params4[v]);
            int4 r0 = __ldcs(&rows4[v]);
            atomicAdd(&out[r0.x], sPw[p0.x] * g0);
            atomicAdd(&out[r0.y], sPw[p0.y] * g1);
            atomicAdd(&out[r0.z], sPw[p0.z] * g2);
            atomicAdd(&out[r0.w], sPw[p0.w] * g3);
        }

        // ---- retire half-batch 1 ----
        if (h2) {
            int4 p1 = __ldcs(&params4[v2]);
            int4 r1 = __ldcs(&rows4[v2]);
            atomicAdd(&out[r1.x], sPw[p1.x] * g4);
            atomicAdd(&out[r1.y], sPw[p1.y] * g5);
            atomicAdd(&out[r1.z], sPw[p1.z] * g6);
            atomicAdd(&out[r1.w], sPw[p1.w] * g7);
        }
    }

    // Tail edges (E % 4 != 0) — defensive; E = 2^24 here.
    if (gtid < tail) {
        int e = E - tail + gtid;
        float val = sPw[params[e]] * __ldg(&x[cols[e]]);
        atomicAdd(&out[rows[e]], val);
    }
}

extern "C" void kernel_launch(void* const* d_in, const int* in_sizes, int n_in,
                              void* d_out, int out_size) {
    // metadata order: x, Param_W, Param_b, w_rows, w_cols, w_params, b_params
    const float* x        = (const float*)d_in[0];
    const float* Param_W  = (const float*)d_in[1];
    const float* Param_b  = (const float*)d_in[2];
    const int*   w_rows   = (const int*)d_in[3];
    const int*   w_cols   = (const int*)d_in[4];
    const int*   w_params = (const int*)d_in[5];
    const int*   b_params = (const int*)d_in[6];
    float*       out      = (float*)d_out;

    const int N = out_size;     // 262144
    const int E = in_sizes[3];  // 16777216

    // 1) bias init (primary PDL kernel; implicit completion trigger at exit)
    {
        int threads = 256;
        int nvec    = N >> 2;
        int blocks  = (nvec + threads - 1) / threads;
        if (blocks < 1) blocks = 1;
        bias_init_kernel<<<blocks, threads>>>(Param_b, b_params, out, N);
    }

    // 2) edge scatter, launched with programmatic stream serialization so its
    //    prologue (smem fill, index/gather issue setup) overlaps bias_init.
    {
        int nvec    = E / 4;
        int tail    = E - nvec * 4;

        cudaLaunchConfig_t cfg = {};
        cfg.gridDim  = dim3(152 * 8, 1, 1);
        cfg.blockDim = dim3(256, 1, 1);
        cfg.dynamicSmemBytes = 0;
        cfg.stream = 0;

        cudaLaunchAttribute attrs[1];
        attrs[0].id = cudaLaunchAttributeProgrammaticStreamSerialization;
        attrs[0].val.programmaticStreamSerializationAllowed = 1;
        cfg.attrs    = attrs;
        cfg.numAttrs = 1;

        cudaLaunchKernelEx(&cfg, edge_scatter_kernel,
                           x, Param_W, w_rows, w_cols, w_params, out,
                           nvec, tail, E);
    }
}